// round 16
// baseline (speedup 1.0000x reference)
#include <cuda_runtime.h>
#include <cstdint>
#include <cstddef>

// Problem constants
#define B_  4
#define T_  2048
#define C_  1024
#define H_  16
#define D_  64
#define M_ROWS (B_ * T_)          // 8192

// Scratch (allocation-free rule: __device__ globals)
__device__ float g_qkv[(size_t)M_ROWS * (3 * C_)];   // [8192, 3072]
__device__ float g_att[(size_t)M_ROWS * C_];         // [8192, 1024]
__device__ float g_xr [(size_t)M_ROWS * C_];         // tf32-rounded x
__device__ float g_war[(size_t)(3 * C_) * C_];       // W_attn^T [3072][1024] tf32
__device__ float g_wpr[(size_t)C_ * C_];             // W_proj^T [1024][1024] tf32

// ---------------------------------------------------------------------------
// helpers
// ---------------------------------------------------------------------------
__device__ __forceinline__ float to_tf32(float x) {
    float y;
    asm("cvt.rna.tf32.f32 %0, %1;" : "=f"(y) : "f"(x));
    return y;
}

__device__ __forceinline__ void mma_tf32(float* d, const uint32_t* a, const uint32_t* b) {
    asm volatile(
        "mma.sync.aligned.m16n8k8.row.col.f32.tf32.tf32.f32 "
        "{%0,%1,%2,%3}, {%4,%5,%6,%7}, {%8,%9}, {%0,%1,%2,%3};\n"
        : "+f"(d[0]), "+f"(d[1]), "+f"(d[2]), "+f"(d[3])
        : "r"(a[0]), "r"(a[1]), "r"(a[2]), "r"(a[3]), "r"(b[0]), "r"(b[1]));
}

__device__ __forceinline__ uint32_t ldsf(const float* p) {
    return __float_as_uint(*p);
}

// ldmatrix x4: four 8x8 b16 tiles (== four 8x4 fp32 blocks for tf32 frags)
__device__ __forceinline__ void ldsm_x4(uint32_t* r, uint32_t smem_addr) {
    asm volatile(
        "ldmatrix.sync.aligned.m8n8.x4.shared.b16 {%0,%1,%2,%3}, [%4];"
        : "=r"(r[0]), "=r"(r[1]), "=r"(r[2]), "=r"(r[3])
        : "r"(smem_addr));
}

__device__ __forceinline__ void cpa16(float* smem_dst, const float* gsrc) {
    uint32_t s = (uint32_t)__cvta_generic_to_shared(smem_dst);
    asm volatile("cp.async.cg.shared.global [%0], [%1], 16;" :: "r"(s), "l"(gsrc));
}
__device__ __forceinline__ void cpa_commit() {
    asm volatile("cp.async.commit_group;");
}
__device__ __forceinline__ void cpa_wait1() {
    asm volatile("cp.async.wait_group 1;");
}
__device__ __forceinline__ void cpa_wait_all() {
    asm volatile("cp.async.wait_group 0;");
}

// ---------------------------------------------------------------------------
// Pre-passes: round x; transpose+round weights to [N][K]
// ---------------------------------------------------------------------------
__global__ void round_x_kernel(const float4* __restrict__ in,
                               float4* __restrict__ out, int n4)
{
    int i = blockIdx.x * blockDim.x + threadIdx.x;
    if (i < n4) {
        float4 v = in[i];
        v.x = to_tf32(v.x); v.y = to_tf32(v.y);
        v.z = to_tf32(v.z); v.w = to_tf32(v.w);
        out[i] = v;
    }
}

// W [K][N] -> Wt [N][K], tf32-rounded.  Wt[n][k] = tf32(W[k][n])
__global__ void transpose_round_kernel(const float* __restrict__ W,
                                       float* __restrict__ Wt, int K, int N)
{
    __shared__ float tile[32][33];
    const int n0 = blockIdx.x * 32;
    const int k0 = blockIdx.y * 32;
    const int tx = threadIdx.x;      // 0..31
    const int ty = threadIdx.y;      // 0..7
    #pragma unroll
    for (int i = 0; i < 32; i += 8)
        tile[ty + i][tx] = W[(size_t)(k0 + ty + i) * N + n0 + tx];
    __syncthreads();
    #pragma unroll
    for (int i = 0; i < 32; i += 8)
        Wt[(size_t)(n0 + ty + i) * K + k0 + tx] = to_tf32(tile[tx][ty + i]);
}

// ---------------------------------------------------------------------------
// GEMM + bias, tf32 tensor cores, 3-stage unrolled cp.async ring (R12/R15-
// proven). BOTH operands via ldmatrix.x4: A [128 m-rows][36], B from
// pre-transposed W^T as [128 n-rows][36] (symmetric layout). Per 8-k step:
// 4 LDSM (A) + 2 LDSM (B) replace 24 scalar LDS. wait_group 1.
// Block 128x128, BK=32, 256 threads (8 warps 2x4, 64x32 each).
// NT = K/32 must be == 2 (mod 3); K=1024 -> NT=32. 10x(0,1,2) + (0,1).
// ---------------------------------------------------------------------------
#define GBM 128
#define GBN 128
#define GBK 32
#define AST 36
#define BST 36
#define A_TILE (GBM * AST)
#define B_TILE (GBN * BST)
#define NSTAGE 3

template<bool ROUND_OUT>
__global__ __launch_bounds__(256) void gemm_tc_kernel(
    const float* __restrict__ A, const float* __restrict__ Wt,
    const float* __restrict__ bias, float* __restrict__ Cmat,
    int M, int N, int K)
{
    extern __shared__ float smem[];
    float* As = smem;                          // NSTAGE stages
    float* Bs = smem + NSTAGE * A_TILE;

    const int tid  = threadIdx.x;
    const int warp = tid >> 5;
    const int lane = tid & 31;
    const int wm   = warp >> 2;
    const int wn   = warp & 3;
    const int gid  = lane >> 2;
    const int tig  = lane & 3;

    const int bm = blockIdx.y * GBM;
    const int bn = blockIdx.x * GBN;

    // ldmatrix lane-address offsets (fp32 units), see R15 mapping proof.
    const int a_lrow = wm * 64 + (lane & 15);
    const int a_lcol = (lane & 16) >> 2;       // 0 or 4
    const int b_lrow = wn * 32 + lane;         // n-row for B tiles

    float acc[4][4][4] = {};

    auto load_tiles = [&](int st, int k0) {
        float* as = As + st * A_TILE;
        float* bs = Bs + st * B_TILE;
        #pragma unroll
        for (int ch = 0; ch < 4; ch++) {
            int idx = ch * 256 + tid;           // 0..1023
            int r  = idx >> 3;                  // 0..127
            int c4 = (idx & 7) * 4;             // 0..28
            cpa16(as + r * AST + c4, A + (size_t)(bm + r) * K + k0 + c4);
        }
        #pragma unroll
        for (int ch = 0; ch < 4; ch++) {
            int idx = ch * 256 + tid;           // 0..1023
            int r  = idx >> 3;                  // 0..127 (n-row)
            int c4 = (idx & 7) * 4;             // 0..28  (k)
            cpa16(bs + r * BST + c4, Wt + (size_t)(bn + r) * K + k0 + c4);
        }
        cpa_commit();
    };

    auto compute_stage = [&](const float* as, const float* bs) {
        const uint32_t as_b = (uint32_t)__cvta_generic_to_shared(as)
                            + (uint32_t)((a_lrow * AST + a_lcol) * 4);
        const uint32_t bs_b = (uint32_t)__cvta_generic_to_shared(bs)
                            + (uint32_t)((b_lrow * BST) * 4);
        #pragma unroll
        for (int ks = 0; ks < GBK; ks += 8) {
            uint32_t af[4][4], b0[4], b1[4];
            #pragma unroll
            for (int mi = 0; mi < 4; mi++)
                ldsm_x4(af[mi], as_b + (uint32_t)((mi * 16 * AST + ks) * 4));
            ldsm_x4(b0, bs_b + (uint32_t)(ks * 4));        // bf[ni][0], k=ks+tig
            ldsm_x4(b1, bs_b + (uint32_t)((ks + 4) * 4));  // bf[ni][1], k=ks+4+tig
            #pragma unroll
            for (int mi = 0; mi < 4; mi++)
                #pragma unroll
                for (int ni = 0; ni < 4; ni++) {
                    uint32_t bp[2] = {b0[ni], b1[ni]};
                    mma_tf32(acc[mi][ni], af[mi], bp);
                }
        }
    };

    const int NT = K / GBK;                    // 32 (==2 mod 3)
    load_tiles(0, 0);
    load_tiles(1, GBK);

#define GEMM_STEP(S, IT)                                                    \
    {                                                                       \
        cpa_wait1();                                                        \
        __syncthreads();                                                    \
        if ((IT) + 2 < NT) load_tiles(((S) + 2) % 3, ((IT) + 2) * GBK);     \
        else               cpa_commit();                                    \
        compute_stage(As + (S) * A_TILE, Bs + (S) * B_TILE);                \
    }

    for (int ib = 0; ib < NT - 2; ib += 3) {
        GEMM_STEP(0, ib);
        GEMM_STEP(1, ib + 1);
        GEMM_STEP(2, ib + 2);
    }
    GEMM_STEP(0, NT - 2);
    GEMM_STEP(1, NT - 1);
#undef GEMM_STEP

    #pragma unroll
    for (int mi = 0; mi < 4; mi++) {
        const int r0 = bm + wm * 64 + mi * 16 + gid;
        #pragma unroll
        for (int ni = 0; ni < 4; ni++) {
            const int c = bn + wn * 32 + ni * 8 + 2 * tig;
            float2 bb = *(const float2*)&bias[c];
            float2 o0, o1;
            o0.x = acc[mi][ni][0] + bb.x;
            o0.y = acc[mi][ni][1] + bb.y;
            o1.x = acc[mi][ni][2] + bb.x;
            o1.y = acc[mi][ni][3] + bb.y;
            if (ROUND_OUT) {
                o0.x = to_tf32(o0.x); o0.y = to_tf32(o0.y);
                o1.x = to_tf32(o1.x); o1.y = to_tf32(o1.y);
            }
            *(float2*)&Cmat[(size_t)r0 * N + c]       = o0;
            *(float2*)&Cmat[(size_t)(r0 + 8) * N + c] = o1;
        }
    }
}

// ---------------------------------------------------------------------------
// Flash attention, tf32 tensor cores, register softmax (R5-proven structure).
// NEW: K fragments via ldmatrix.x4 (4 LDSM replace 16 scalar LDS per ks step;
// K smem is already key-major so no layout change). V loop stays scalar.
// Grid (32 q-tiles, 64 bh), 128 threads = 4 warps; warp owns 16 q-rows.
// Heavy q-tiles first. K/V double-buffered cp.async, 1 barrier per tile.
// ---------------------------------------------------------------------------
#define KST 68
#define VST 72
#define K_TILE (64 * KST)
#define V_TILE (64 * VST)

__global__ __launch_bounds__(128) void attn_tc2_kernel(
    const float* __restrict__ qkv, float* __restrict__ y)
{
    const int qt = (int)gridDim.x - 1 - (int)blockIdx.x;   // heavy tiles first
    const int bh = blockIdx.y;
    const int b  = bh >> 4;
    const int h  = bh & 15;

    extern __shared__ float sm[];
    float* Ks = sm;                    // [2][64*KST]
    float* Vs = sm + 2 * K_TILE;       // [2][64*VST]

    const int tid  = threadIdx.x;
    const int warp = tid >> 5;
    const int lane = tid & 31;
    const int gid  = lane >> 2;
    const int tig  = lane & 3;

    const size_t qkv_row0 = (size_t)(b * T_) * (3 * C_);
    const int hc = h * D_;

    // ---- Stage Q into Ks[0], then pull fragments into registers ----
    {
        #pragma unroll
        for (int ch = 0; ch < 8; ch++) {
            int idx = ch * 128 + tid;          // 0..1023
            int r  = idx >> 4;
            int c4 = (idx & 15) * 4;
            float4 v = *(const float4*)(qkv + qkv_row0
                         + (size_t)(qt * 64 + r) * (3 * C_) + hc + c4);
            *(float4*)&Ks[r * KST + c4] = v;
        }
    }
    __syncthreads();

    uint32_t qf[8][4];
    {
        const int r = warp * 16 + gid;
        #pragma unroll
        for (int ks = 0; ks < 8; ks++) {
            const int c = ks * 8 + tig;
            qf[ks][0] = __float_as_uint(Ks[r * KST + c] * 0.125f);
            qf[ks][1] = __float_as_uint(Ks[(r + 8) * KST + c] * 0.125f);
            qf[ks][2] = __float_as_uint(Ks[r * KST + c + 4] * 0.125f);
            qf[ks][3] = __float_as_uint(Ks[(r + 8) * KST + c + 4] * 0.125f);
        }
    }
    __syncthreads();

    auto load_kv = [&](int st, int kt) {
        float* kd = Ks + st * K_TILE;
        float* vd = Vs + st * V_TILE;
        const size_t base = qkv_row0 + (size_t)(kt * 64) * (3 * C_) + hc;
        #pragma unroll
        for (int ch = 0; ch < 8; ch++) {
            int idx = ch * 128 + tid;
            int r  = idx >> 4;
            int c4 = (idx & 15) * 4;
            const size_t roff = base + (size_t)r * (3 * C_);
            cpa16(kd + r * KST + c4, qkv + roff + C_ + c4);
            cpa16(vd + r * VST + c4, qkv + roff + 2 * C_ + c4);
        }
        cpa_commit();
    };

    load_kv(0, 0);

    float acc_o[8][4] = {};
    float m0 = -1e30f, m1 = -1e30f, l0 = 0.0f, l1 = 0.0f;
    const int r_loc0 = warp * 16 + gid;
    const int r_loc1 = r_loc0 + 8;

    for (int kt = 0; kt <= qt; kt++) {
        cpa_wait_all();
        __syncthreads();
        const int st = kt & 1;
        if (kt < qt) load_kv(st ^ 1, kt + 1);

        const float* ks_ = Ks + st * K_TILE;
        const float* vs_ = Vs + st * V_TILE;

        // ---- S = Q @ K^T : 16 x 64 per warp, K frags via ldmatrix ----
        // lane l addresses key-row `lane` (tiles ni=0..3) / `32+lane` (ni=4..7)
        const uint32_t km0 = (uint32_t)__cvta_generic_to_shared(ks_)
                           + (uint32_t)((lane * KST) * 4);
        const uint32_t km1 = (uint32_t)__cvta_generic_to_shared(ks_)
                           + (uint32_t)(((32 + lane) * KST) * 4);
        float s[8][4] = {};
        #pragma unroll
        for (int ks = 0; ks < 8; ks++) {
            uint32_t b0[4], b1[4], b2[4], b3[4];
            ldsm_x4(b0, km0 + (uint32_t)(ks * 32));        // keys 0-31,  d=ks*8+tig
            ldsm_x4(b1, km0 + (uint32_t)(ks * 32 + 16));   // keys 0-31,  d+4
            ldsm_x4(b2, km1 + (uint32_t)(ks * 32));        // keys 32-63, d
            ldsm_x4(b3, km1 + (uint32_t)(ks * 32 + 16));   // keys 32-63, d+4
            #pragma unroll
            for (int ni = 0; ni < 4; ni++) {
                uint32_t bp[2] = {b0[ni], b1[ni]};
                mma_tf32(s[ni], qf[ks], bp);
                uint32_t bq[2] = {b2[ni], b3[ni]};
                mma_tf32(s[ni + 4], qf[ks], bq);
            }
        }

        // ---- causal mask (diagonal tile only) ----
        if (kt == qt) {
            #pragma unroll
            for (int ni = 0; ni < 8; ni++) {
                const int c = ni * 8 + 2 * tig;
                if (c > r_loc0)     s[ni][0] = -1e30f;
                if (c + 1 > r_loc0) s[ni][1] = -1e30f;
                if (c > r_loc1)     s[ni][2] = -1e30f;
                if (c + 1 > r_loc1) s[ni][3] = -1e30f;
            }
        }

        // ---- register online softmax (rows warp-local) ----
        float mx0 = -1e30f, mx1 = -1e30f;
        #pragma unroll
        for (int ni = 0; ni < 8; ni++) {
            mx0 = fmaxf(mx0, fmaxf(s[ni][0], s[ni][1]));
            mx1 = fmaxf(mx1, fmaxf(s[ni][2], s[ni][3]));
        }
        mx0 = fmaxf(mx0, __shfl_xor_sync(0xffffffffu, mx0, 1));
        mx0 = fmaxf(mx0, __shfl_xor_sync(0xffffffffu, mx0, 2));
        mx1 = fmaxf(mx1, __shfl_xor_sync(0xffffffffu, mx1, 1));
        mx1 = fmaxf(mx1, __shfl_xor_sync(0xffffffffu, mx1, 2));

        const float mn0 = fmaxf(m0, mx0);
        const float mn1 = fmaxf(m1, mx1);
        const float al0 = __expf(m0 - mn0);
        const float al1 = __expf(m1 - mn1);
        m0 = mn0; m1 = mn1;

        float sum0 = 0.0f, sum1 = 0.0f;
        #pragma unroll
        for (int ni = 0; ni < 8; ni++) {
            float p0 = __expf(s[ni][0] - mn0);
            float p1 = __expf(s[ni][1] - mn0);
            float p2 = __expf(s[ni][2] - mn1);
            float p3 = __expf(s[ni][3] - mn1);
            sum0 += p0 + p1; sum1 += p2 + p3;
            s[ni][0] = to_tf32(p0); s[ni][1] = to_tf32(p1);
            s[ni][2] = to_tf32(p2); s[ni][3] = to_tf32(p3);
        }
        sum0 += __shfl_xor_sync(0xffffffffu, sum0, 1);
        sum0 += __shfl_xor_sync(0xffffffffu, sum0, 2);
        sum1 += __shfl_xor_sync(0xffffffffu, sum1, 1);
        sum1 += __shfl_xor_sync(0xffffffffu, sum1, 2);
        l0 = l0 * al0 + sum0;
        l1 = l1 * al1 + sum1;

        #pragma unroll
        for (int ni = 0; ni < 8; ni++) {
            acc_o[ni][0] *= al0; acc_o[ni][1] *= al0;
            acc_o[ni][2] *= al1; acc_o[ni][3] *= al1;
        }

        // ---- O += P @ V : P accum -> A-frag via shfl relayout ----
        const int base = lane & ~3;
        const int srcA = base + (tig >> 1);
        const bool odd = tig & 1;
        #pragma unroll
        for (int ks = 0; ks < 8; ks++) {
            float t0 = __shfl_sync(0xffffffffu, s[ks][0], srcA);
            float t1 = __shfl_sync(0xffffffffu, s[ks][1], srcA);
            float t2 = __shfl_sync(0xffffffffu, s[ks][2], srcA);
            float t3 = __shfl_sync(0xffffffffu, s[ks][3], srcA);
            float u0 = __shfl_sync(0xffffffffu, s[ks][0], srcA + 2);
            float u1 = __shfl_sync(0xffffffffu, s[ks][1], srcA + 2);
            float u2 = __shfl_sync(0xffffffffu, s[ks][2], srcA + 2);
            float u3 = __shfl_sync(0xffffffffu, s[ks][3], srcA + 2);
            uint32_t af[4];
            af[0] = __float_as_uint(odd ? t1 : t0);   // (gid,   tig)
            af[1] = __float_as_uint(odd ? t3 : t2);   // (gid+8, tig)
            af[2] = __float_as_uint(odd ? u1 : u0);   // (gid,   tig+4)
            af[3] = __float_as_uint(odd ? u3 : u2);   // (gid+8, tig+4)

            const int kr = ks * 8 + tig;              // key row (k dim)
            uint32_t bf[8][2];
            #pragma unroll
            for (int ni = 0; ni < 8; ni++) {
                const int n = ni * 8 + gid;           // d index
                bf[ni][0] = ldsf(&vs_[kr * VST + n]);
                bf[ni][1] = ldsf(&vs_[(kr + 4) * VST + n]);
            }
            #pragma unroll
            for (int ni = 0; ni < 8; ni++)
                mma_tf32(acc_o[ni], af, bf[ni]);
        }
    }

    // ---- epilogue: normalize, tf32-round (A operand of proj GEMM), store ----
    {
        const float inv0 = 1.0f / l0;
        const float inv1 = 1.0f / l1;
        float* dst0 = &y[(size_t)(b * T_ + qt * 64 + r_loc0) * C_ + hc];
        float* dst1 = &y[(size_t)(b * T_ + qt * 64 + r_loc1) * C_ + hc];
        #pragma unroll
        for (int ni = 0; ni < 8; ni++) {
            const int c = ni * 8 + 2 * tig;
            float2 o0, o1;
            o0.x = to_tf32(acc_o[ni][0] * inv0);
            o0.y = to_tf32(acc_o[ni][1] * inv0);
            o1.x = to_tf32(acc_o[ni][2] * inv1);
            o1.y = to_tf32(acc_o[ni][3] * inv1);
            *(float2*)(dst0 + c) = o0;
            *(float2*)(dst1 + c) = o1;
        }
    }
}

// ---------------------------------------------------------------------------
// Launch
// ---------------------------------------------------------------------------
extern "C" void kernel_launch(void* const* d_in, const int* in_sizes, int n_in,
                              void* d_out, int out_size)
{
    const float* x      = (const float*)d_in[0];
    const float* w_attn = (const float*)d_in[1];
    const float* b_attn = (const float*)d_in[2];
    const float* w_proj = (const float*)d_in[3];
    const float* b_proj = (const float*)d_in[4];
    float* out = (float*)d_out;

    float *qkv, *att, *xr, *war, *wpr;
    cudaGetSymbolAddress((void**)&qkv, g_qkv);
    cudaGetSymbolAddress((void**)&att, g_att);
    cudaGetSymbolAddress((void**)&xr,  g_xr);
    cudaGetSymbolAddress((void**)&war, g_war);
    cudaGetSymbolAddress((void**)&wpr, g_wpr);

    const int gemm_smem = NSTAGE * (A_TILE + B_TILE) * (int)sizeof(float);  // 110592
    const int attn_smem = (2 * K_TILE + 2 * V_TILE) * (int)sizeof(float);   // 71680
    cudaFuncSetAttribute(gemm_tc_kernel<true>,
                         cudaFuncAttributeMaxDynamicSharedMemorySize, gemm_smem);
    cudaFuncSetAttribute(gemm_tc_kernel<false>,
                         cudaFuncAttributeMaxDynamicSharedMemorySize, gemm_smem);
    cudaFuncSetAttribute(attn_tc2_kernel,
                         cudaFuncAttributeMaxDynamicSharedMemorySize, attn_smem);

    // 0) pre-passes: round x; transpose+round weights to [N][K]
    {
        int n4x = (M_ROWS * C_) / 4;
        round_x_kernel<<<(n4x + 255) / 256, 256>>>((const float4*)x, (float4*)xr, n4x);
        transpose_round_kernel<<<dim3((3 * C_) / 32, C_ / 32), dim3(32, 8)>>>(
            w_attn, war, C_, 3 * C_);
        transpose_round_kernel<<<dim3(C_ / 32, C_ / 32), dim3(32, 8)>>>(
            w_proj, wpr, C_, C_);
    }

    // 1) qkv = x @ W_attn + b_attn (tf32-rounded output for attention)
    gemm_tc_kernel<true><<<dim3((3 * C_) / GBN, M_ROWS / GBM), 256, gemm_smem>>>(
        xr, war, b_attn, qkv, M_ROWS, 3 * C_, C_);

    // 2) flash attention -> att (tf32-rounded output for proj)
    attn_tc2_kernel<<<dim3(T_ / 64, B_ * H_), 128, attn_smem>>>(qkv, att);

    // 3) out = att @ W_proj + b_proj (full fp32 output)
    gemm_tc_kernel<false><<<dim3(C_ / GBN, M_ROWS / GBM), 256, gemm_smem>>>(
        att, wpr, b_proj, out, M_ROWS, C_, C_);
}

// round 17
// speedup vs baseline: 1.0914x; 1.0914x over previous
#include <cuda_runtime.h>
#include <cstdint>
#include <cstddef>

// Problem constants
#define B_  4
#define T_  2048
#define C_  1024
#define H_  16
#define D_  64
#define M_ROWS (B_ * T_)          // 8192

// Scratch (allocation-free rule: __device__ globals)
__device__ float g_qkv[(size_t)M_ROWS * (3 * C_)];   // [8192, 3072]
__device__ float g_att[(size_t)M_ROWS * C_];         // [8192, 1024]
__device__ float g_xr [(size_t)M_ROWS * C_];         // tf32-rounded x
__device__ float g_war[(size_t)C_ * (3 * C_)];       // tf32-rounded c_attn_w
__device__ float g_wpr[(size_t)C_ * C_];             // tf32-rounded c_proj_w

// ---------------------------------------------------------------------------
// helpers
// ---------------------------------------------------------------------------
__device__ __forceinline__ float to_tf32(float x) {
    float y;
    asm("cvt.rna.tf32.f32 %0, %1;" : "=f"(y) : "f"(x));
    return y;
}

__device__ __forceinline__ void mma_tf32(float* d, const uint32_t* a, const uint32_t* b) {
    asm volatile(
        "mma.sync.aligned.m16n8k8.row.col.f32.tf32.tf32.f32 "
        "{%0,%1,%2,%3}, {%4,%5,%6,%7}, {%8,%9}, {%0,%1,%2,%3};\n"
        : "+f"(d[0]), "+f"(d[1]), "+f"(d[2]), "+f"(d[3])
        : "r"(a[0]), "r"(a[1]), "r"(a[2]), "r"(a[3]), "r"(b[0]), "r"(b[1]));
}

// mma with B operand given as two separate regs (no array repack)
__device__ __forceinline__ void mma_tf32_b2(float* d, const uint32_t* a,
                                            uint32_t b0, uint32_t b1) {
    asm volatile(
        "mma.sync.aligned.m16n8k8.row.col.f32.tf32.tf32.f32 "
        "{%0,%1,%2,%3}, {%4,%5,%6,%7}, {%8,%9}, {%0,%1,%2,%3};\n"
        : "+f"(d[0]), "+f"(d[1]), "+f"(d[2]), "+f"(d[3])
        : "r"(a[0]), "r"(a[1]), "r"(a[2]), "r"(a[3]), "r"(b0), "r"(b1));
}

__device__ __forceinline__ uint32_t ldsf(const float* p) {
    return __float_as_uint(*p);
}

// ldmatrix x4: four 8x8 b16 tiles (== four 8x4 fp32 blocks for tf32 frags)
__device__ __forceinline__ void ldsm_x4(uint32_t* r, uint32_t smem_addr) {
    asm volatile(
        "ldmatrix.sync.aligned.m8n8.x4.shared.b16 {%0,%1,%2,%3}, [%4];"
        : "=r"(r[0]), "=r"(r[1]), "=r"(r[2]), "=r"(r[3])
        : "r"(smem_addr));
}

__device__ __forceinline__ void cpa16(float* smem_dst, const float* gsrc) {
    uint32_t s = (uint32_t)__cvta_generic_to_shared(smem_dst);
    asm volatile("cp.async.cg.shared.global [%0], [%1], 16;" :: "r"(s), "l"(gsrc));
}
__device__ __forceinline__ void cpa_commit() {
    asm volatile("cp.async.commit_group;");
}
__device__ __forceinline__ void cpa_wait1() {
    asm volatile("cp.async.wait_group 1;");
}
__device__ __forceinline__ void cpa_wait_all() {
    asm volatile("cp.async.wait_group 0;");
}

// ---------------------------------------------------------------------------
// tf32 pre-rounding: ONE kernel for all three arrays
// ---------------------------------------------------------------------------
#define N4_X  ((M_ROWS * C_) / 4)          // 2097152
#define N4_WA ((C_ * 3 * C_) / 4)          // 786432
#define N4_WP ((C_ * C_) / 4)              // 262144

__global__ void round_all_kernel(const float4* __restrict__ x,   float4* __restrict__ xr,
                                 const float4* __restrict__ wa,  float4* __restrict__ war,
                                 const float4* __restrict__ wp,  float4* __restrict__ wpr)
{
    int i = blockIdx.x * blockDim.x + threadIdx.x;
    const float4* src;
    float4* dst;
    int j;
    if (i < N4_X)                      { src = x;  dst = xr;  j = i; }
    else if (i < N4_X + N4_WA)         { src = wa; dst = war; j = i - N4_X; }
    else if (i < N4_X + N4_WA + N4_WP) { src = wp; dst = wpr; j = i - N4_X - N4_WA; }
    else return;
    float4 v = src[j];
    v.x = to_tf32(v.x); v.y = to_tf32(v.y);
    v.z = to_tf32(v.z); v.w = to_tf32(v.w);
    dst[j] = v;
}

// ---------------------------------------------------------------------------
// GEMM + bias, tf32 tensor cores, 3-stage unrolled cp.async ring.
// A fragments via ldmatrix.x4, B fragments scalar (R15-proven exact config).
// Block 128x128, BK=32, 256 threads (8 warps 2x4, 64x32 each).
// As [stage][128][36], Bs [stage][32][136].
// NT = K/32 must be == 2 (mod 3); K=1024 -> NT=32. 10x(0,1,2) + (0,1).
// ---------------------------------------------------------------------------
#define GBM 128
#define GBN 128
#define GBK 32
#define AST 36
#define BST 136
#define A_TILE (GBM * AST)
#define B_TILE (GBK * BST)
#define NSTAGE 3

template<bool ROUND_OUT>
__global__ __launch_bounds__(256) void gemm_tc_kernel(
    const float* __restrict__ A, const float* __restrict__ W,
    const float* __restrict__ bias, float* __restrict__ Cmat,
    int M, int N, int K)
{
    extern __shared__ float smem[];
    float* As = smem;                          // NSTAGE stages
    float* Bs = smem + NSTAGE * A_TILE;

    const int tid  = threadIdx.x;
    const int warp = tid >> 5;
    const int lane = tid & 31;
    const int wm   = warp >> 2;
    const int wn   = warp & 3;
    const int gid  = lane >> 2;
    const int tig  = lane & 3;

    const int bm = blockIdx.y * GBM;
    const int bn = blockIdx.x * GBN;

    const int a_lrow = wm * 64 + (lane & 15);
    const int a_lcol = (lane & 16) >> 2;       // 0 or 4

    float acc[4][4][4] = {};

    auto load_tiles = [&](int st, int k0) {
        float* as = As + st * A_TILE;
        float* bs = Bs + st * B_TILE;
        #pragma unroll
        for (int ch = 0; ch < 4; ch++) {
            int idx = ch * 256 + tid;           // 0..1023
            int r  = idx >> 3;                  // 0..127
            int c4 = (idx & 7) * 4;             // 0..28
            cpa16(as + r * AST + c4, A + (size_t)(bm + r) * K + k0 + c4);
        }
        #pragma unroll
        for (int ch = 0; ch < 4; ch++) {
            int idx = ch * 256 + tid;
            int r  = idx >> 5;                  // 0..31
            int c4 = (idx & 31) * 4;            // 0..124
            cpa16(bs + r * BST + c4, W + (size_t)(k0 + r) * N + bn + c4);
        }
        cpa_commit();
    };

    auto compute_stage = [&](const float* as, const float* bs) {
        const uint32_t as_b = (uint32_t)__cvta_generic_to_shared(as)
                            + (uint32_t)((a_lrow * AST + a_lcol) * 4);
        #pragma unroll
        for (int ks = 0; ks < GBK; ks += 8) {
            uint32_t af[4][4], bf[4][2];
            #pragma unroll
            for (int mi = 0; mi < 4; mi++)
                ldsm_x4(af[mi], as_b + (uint32_t)((mi * 16 * AST + ks) * 4));
            #pragma unroll
            for (int ni = 0; ni < 4; ni++) {
                const int n = wn * 32 + ni * 8 + gid;
                const int k = ks + tig;
                bf[ni][0] = ldsf(&bs[k * BST + n]);
                bf[ni][1] = ldsf(&bs[(k + 4) * BST + n]);
            }
            #pragma unroll
            for (int mi = 0; mi < 4; mi++)
                #pragma unroll
                for (int ni = 0; ni < 4; ni++)
                    mma_tf32(acc[mi][ni], af[mi], bf[ni]);
        }
    };

    const int NT = K / GBK;                    // 32 (==2 mod 3)
    load_tiles(0, 0);
    load_tiles(1, GBK);

#define GEMM_STEP(S, IT)                                                    \
    {                                                                       \
        cpa_wait1();                                                        \
        __syncthreads();                                                    \
        if ((IT) + 2 < NT) load_tiles(((S) + 2) % 3, ((IT) + 2) * GBK);     \
        else               cpa_commit();                                    \
        compute_stage(As + (S) * A_TILE, Bs + (S) * B_TILE);                \
    }

    for (int ib = 0; ib < NT - 2; ib += 3) {
        GEMM_STEP(0, ib);
        GEMM_STEP(1, ib + 1);
        GEMM_STEP(2, ib + 2);
    }
    GEMM_STEP(0, NT - 2);
    GEMM_STEP(1, NT - 1);
#undef GEMM_STEP

    #pragma unroll
    for (int mi = 0; mi < 4; mi++) {
        const int r0 = bm + wm * 64 + mi * 16 + gid;
        #pragma unroll
        for (int ni = 0; ni < 4; ni++) {
            const int c = bn + wn * 32 + ni * 8 + 2 * tig;
            float2 bb = *(const float2*)&bias[c];
            float2 o0, o1;
            o0.x = acc[mi][ni][0] + bb.x;
            o0.y = acc[mi][ni][1] + bb.y;
            o1.x = acc[mi][ni][2] + bb.x;
            o1.y = acc[mi][ni][3] + bb.y;
            if (ROUND_OUT) {
                o0.x = to_tf32(o0.x); o0.y = to_tf32(o0.y);
                o1.x = to_tf32(o1.x); o1.y = to_tf32(o1.y);
            }
            *(float2*)&Cmat[(size_t)r0 * N + c]       = o0;
            *(float2*)&Cmat[(size_t)(r0 + 8) * N + c] = o1;
        }
    }
}

// ---------------------------------------------------------------------------
// Flash attention, tf32 tensor cores, register softmax (R5-proven structure)
// + K fragments via ldmatrix.x4 (validated bit-exact in R16).
// Grid (32 q-tiles, 64 bh), 128 threads = 4 warps; warp owns 16 q-rows.
// Heavy q-tiles first. K/V double-buffered cp.async, 1 barrier per tile.
// ---------------------------------------------------------------------------
#define KST 68
#define VST 72
#define K_TILE (64 * KST)
#define V_TILE (64 * VST)

__global__ __launch_bounds__(128) void attn_tc2_kernel(
    const float* __restrict__ qkv, float* __restrict__ y)
{
    const int qt = (int)gridDim.x - 1 - (int)blockIdx.x;   // heavy tiles first
    const int bh = blockIdx.y;
    const int b  = bh >> 4;
    const int h  = bh & 15;

    extern __shared__ float sm[];
    float* Ks = sm;                    // [2][64*KST]
    float* Vs = sm + 2 * K_TILE;       // [2][64*VST]

    const int tid  = threadIdx.x;
    const int warp = tid >> 5;
    const int lane = tid & 31;
    const int gid  = lane >> 2;
    const int tig  = lane & 3;

    const size_t qkv_row0 = (size_t)(b * T_) * (3 * C_);
    const int hc = h * D_;

    // ---- Stage Q into Ks[0], then pull fragments into registers ----
    {
        #pragma unroll
        for (int ch = 0; ch < 8; ch++) {
            int idx = ch * 128 + tid;          // 0..1023
            int r  = idx >> 4;
            int c4 = (idx & 15) * 4;
            float4 v = *(const float4*)(qkv + qkv_row0
                         + (size_t)(qt * 64 + r) * (3 * C_) + hc + c4);
            *(float4*)&Ks[r * KST + c4] = v;
        }
    }
    __syncthreads();

    uint32_t qf[8][4];
    {
        const int r = warp * 16 + gid;
        #pragma unroll
        for (int ks = 0; ks < 8; ks++) {
            const int c = ks * 8 + tig;
            qf[ks][0] = __float_as_uint(Ks[r * KST + c] * 0.125f);
            qf[ks][1] = __float_as_uint(Ks[(r + 8) * KST + c] * 0.125f);
            qf[ks][2] = __float_as_uint(Ks[r * KST + c + 4] * 0.125f);
            qf[ks][3] = __float_as_uint(Ks[(r + 8) * KST + c + 4] * 0.125f);
        }
    }
    __syncthreads();

    auto load_kv = [&](int st, int kt) {
        float* kd = Ks + st * K_TILE;
        float* vd = Vs + st * V_TILE;
        const size_t base = qkv_row0 + (size_t)(kt * 64) * (3 * C_) + hc;
        #pragma unroll
        for (int ch = 0; ch < 8; ch++) {
            int idx = ch * 128 + tid;
            int r  = idx >> 4;
            int c4 = (idx & 15) * 4;
            const size_t roff = base + (size_t)r * (3 * C_);
            cpa16(kd + r * KST + c4, qkv + roff + C_ + c4);
            cpa16(vd + r * VST + c4, qkv + roff + 2 * C_ + c4);
        }
        cpa_commit();
    };

    load_kv(0, 0);

    float acc_o[8][4] = {};
    float m0 = -1e30f, m1 = -1e30f, l0 = 0.0f, l1 = 0.0f;
    const int r_loc0 = warp * 16 + gid;
    const int r_loc1 = r_loc0 + 8;

    for (int kt = 0; kt <= qt; kt++) {
        cpa_wait_all();
        __syncthreads();
        const int st = kt & 1;
        if (kt < qt) load_kv(st ^ 1, kt + 1);

        const float* ks_ = Ks + st * K_TILE;
        const float* vs_ = Vs + st * V_TILE;

        // ---- S = Q @ K^T : 16 x 64 per warp, K frags via ldmatrix ----
        const uint32_t km0 = (uint32_t)__cvta_generic_to_shared(ks_)
                           + (uint32_t)((lane * KST) * 4);
        const uint32_t km1 = (uint32_t)__cvta_generic_to_shared(ks_)
                           + (uint32_t)(((32 + lane) * KST) * 4);
        float s[8][4] = {};
        #pragma unroll
        for (int ks = 0; ks < 8; ks++) {
            uint32_t b0[4], b1[4], b2[4], b3[4];
            ldsm_x4(b0, km0 + (uint32_t)(ks * 32));        // keys 0-31,  d=ks*8+tig
            ldsm_x4(b1, km0 + (uint32_t)(ks * 32 + 16));   // keys 0-31,  d+4
            ldsm_x4(b2, km1 + (uint32_t)(ks * 32));        // keys 32-63, d
            ldsm_x4(b3, km1 + (uint32_t)(ks * 32 + 16));   // keys 32-63, d+4
            #pragma unroll
            for (int ni = 0; ni < 4; ni++) {
                mma_tf32_b2(s[ni],     qf[ks], b0[ni], b1[ni]);
                mma_tf32_b2(s[ni + 4], qf[ks], b2[ni], b3[ni]);
            }
        }

        // ---- causal mask (diagonal tile only) ----
        if (kt == qt) {
            #pragma unroll
            for (int ni = 0; ni < 8; ni++) {
                const int c = ni * 8 + 2 * tig;
                if (c > r_loc0)     s[ni][0] = -1e30f;
                if (c + 1 > r_loc0) s[ni][1] = -1e30f;
                if (c > r_loc1)     s[ni][2] = -1e30f;
                if (c + 1 > r_loc1) s[ni][3] = -1e30f;
            }
        }

        // ---- register online softmax (rows warp-local) ----
        float mx0 = -1e30f, mx1 = -1e30f;
        #pragma unroll
        for (int ni = 0; ni < 8; ni++) {
            mx0 = fmaxf(mx0, fmaxf(s[ni][0], s[ni][1]));
            mx1 = fmaxf(mx1, fmaxf(s[ni][2], s[ni][3]));
        }
        mx0 = fmaxf(mx0, __shfl_xor_sync(0xffffffffu, mx0, 1));
        mx0 = fmaxf(mx0, __shfl_xor_sync(0xffffffffu, mx0, 2));
        mx1 = fmaxf(mx1, __shfl_xor_sync(0xffffffffu, mx1, 1));
        mx1 = fmaxf(mx1, __shfl_xor_sync(0xffffffffu, mx1, 2));

        const float mn0 = fmaxf(m0, mx0);
        const float mn1 = fmaxf(m1, mx1);
        const float al0 = __expf(m0 - mn0);
        const float al1 = __expf(m1 - mn1);
        m0 = mn0; m1 = mn1;

        float sum0 = 0.0f, sum1 = 0.0f;
        #pragma unroll
        for (int ni = 0; ni < 8; ni++) {
            float p0 = __expf(s[ni][0] - mn0);
            float p1 = __expf(s[ni][1] - mn0);
            float p2 = __expf(s[ni][2] - mn1);
            float p3 = __expf(s[ni][3] - mn1);
            sum0 += p0 + p1; sum1 += p2 + p3;
            s[ni][0] = to_tf32(p0); s[ni][1] = to_tf32(p1);
            s[ni][2] = to_tf32(p2); s[ni][3] = to_tf32(p3);
        }
        sum0 += __shfl_xor_sync(0xffffffffu, sum0, 1);
        sum0 += __shfl_xor_sync(0xffffffffu, sum0, 2);
        sum1 += __shfl_xor_sync(0xffffffffu, sum1, 1);
        sum1 += __shfl_xor_sync(0xffffffffu, sum1, 2);
        l0 = l0 * al0 + sum0;
        l1 = l1 * al1 + sum1;

        #pragma unroll
        for (int ni = 0; ni < 8; ni++) {
            acc_o[ni][0] *= al0; acc_o[ni][1] *= al0;
            acc_o[ni][2] *= al1; acc_o[ni][3] *= al1;
        }

        // ---- O += P @ V : P accum -> A-frag via shfl relayout ----
        const int base = lane & ~3;
        const int srcA = base + (tig >> 1);
        const bool odd = tig & 1;
        #pragma unroll
        for (int ks = 0; ks < 8; ks++) {
            float t0 = __shfl_sync(0xffffffffu, s[ks][0], srcA);
            float t1 = __shfl_sync(0xffffffffu, s[ks][1], srcA);
            float t2 = __shfl_sync(0xffffffffu, s[ks][2], srcA);
            float t3 = __shfl_sync(0xffffffffu, s[ks][3], srcA);
            float u0 = __shfl_sync(0xffffffffu, s[ks][0], srcA + 2);
            float u1 = __shfl_sync(0xffffffffu, s[ks][1], srcA + 2);
            float u2 = __shfl_sync(0xffffffffu, s[ks][2], srcA + 2);
            float u3 = __shfl_sync(0xffffffffu, s[ks][3], srcA + 2);
            uint32_t af[4];
            af[0] = __float_as_uint(odd ? t1 : t0);   // (gid,   tig)
            af[1] = __float_as_uint(odd ? t3 : t2);   // (gid+8, tig)
            af[2] = __float_as_uint(odd ? u1 : u0);   // (gid,   tig+4)
            af[3] = __float_as_uint(odd ? u3 : u2);   // (gid+8, tig+4)

            const int kr = ks * 8 + tig;              // key row (k dim)
            uint32_t bf[8][2];
            #pragma unroll
            for (int ni = 0; ni < 8; ni++) {
                const int n = ni * 8 + gid;           // d index
                bf[ni][0] = ldsf(&vs_[kr * VST + n]);
                bf[ni][1] = ldsf(&vs_[(kr + 4) * VST + n]);
            }
            #pragma unroll
            for (int ni = 0; ni < 8; ni++)
                mma_tf32(acc_o[ni], af, bf[ni]);
        }
    }

    // ---- epilogue: normalize, tf32-round (A operand of proj GEMM), store ----
    {
        const float inv0 = 1.0f / l0;
        const float inv1 = 1.0f / l1;
        float* dst0 = &y[(size_t)(b * T_ + qt * 64 + r_loc0) * C_ + hc];
        float* dst1 = &y[(size_t)(b * T_ + qt * 64 + r_loc1) * C_ + hc];
        #pragma unroll
        for (int ni = 0; ni < 8; ni++) {
            const int c = ni * 8 + 2 * tig;
            float2 o0, o1;
            o0.x = to_tf32(acc_o[ni][0] * inv0);
            o0.y = to_tf32(acc_o[ni][1] * inv0);
            o1.x = to_tf32(acc_o[ni][2] * inv1);
            o1.y = to_tf32(acc_o[ni][3] * inv1);
            *(float2*)(dst0 + c) = o0;
            *(float2*)(dst1 + c) = o1;
        }
    }
}

// ---------------------------------------------------------------------------
// Launch
// ---------------------------------------------------------------------------
extern "C" void kernel_launch(void* const* d_in, const int* in_sizes, int n_in,
                              void* d_out, int out_size)
{
    const float* x      = (const float*)d_in[0];
    const float* w_attn = (const float*)d_in[1];
    const float* b_attn = (const float*)d_in[2];
    const float* w_proj = (const float*)d_in[3];
    const float* b_proj = (const float*)d_in[4];
    float* out = (float*)d_out;

    float *qkv, *att, *xr, *war, *wpr;
    cudaGetSymbolAddress((void**)&qkv, g_qkv);
    cudaGetSymbolAddress((void**)&att, g_att);
    cudaGetSymbolAddress((void**)&xr,  g_xr);
    cudaGetSymbolAddress((void**)&war, g_war);
    cudaGetSymbolAddress((void**)&wpr, g_wpr);

    const int gemm_smem = NSTAGE * (A_TILE + B_TILE) * (int)sizeof(float);  // 107520
    const int attn_smem = (2 * K_TILE + 2 * V_TILE) * (int)sizeof(float);   // 71680
    cudaFuncSetAttribute(gemm_tc_kernel<true>,
                         cudaFuncAttributeMaxDynamicSharedMemorySize, gemm_smem);
    cudaFuncSetAttribute(gemm_tc_kernel<false>,
                         cudaFuncAttributeMaxDynamicSharedMemorySize, gemm_smem);
    cudaFuncSetAttribute(attn_tc2_kernel,
                         cudaFuncAttributeMaxDynamicSharedMemorySize, attn_smem);

    // 0) tf32 pre-rounding of all GEMM inputs (single launch)
    {
        int n4 = N4_X + N4_WA + N4_WP;
        round_all_kernel<<<(n4 + 255) / 256, 256>>>(
            (const float4*)x, (float4*)xr,
            (const float4*)w_attn, (float4*)war,
            (const float4*)w_proj, (float4*)wpr);
    }

    // 1) qkv = x @ W_attn + b_attn (tf32-rounded output for attention)
    gemm_tc_kernel<true><<<dim3((3 * C_) / GBN, M_ROWS / GBM), 256, gemm_smem>>>(
        xr, war, b_attn, qkv, M_ROWS, 3 * C_, C_);

    // 2) flash attention -> att (tf32-rounded output for proj)
    attn_tc2_kernel<<<dim3(T_ / 64, B_ * H_), 128, attn_smem>>>(qkv, att);

    // 3) out = att @ W_proj + b_proj (full fp32 output)
    gemm_tc_kernel<false><<<dim3(C_ / GBN, M_ROWS / GBM), 256, gemm_smem>>>(
        att, wpr, b_proj, out, M_ROWS, C_, C_);
}